// round 15
// baseline (speedup 1.0000x reference)
#include <cuda_runtime.h>
#include <cstdint>

// Inverse 2D Haar wavelet (synthesis), fixed shapes:
//   in : (B=32, C4=256, H=64, W=64) f32   (C4 = C*4: cA,cH,cV,cD per channel)
//   out: (B=32, C=64, 128, 128) f32
//
// Final config-matrix probe: proven warp-per-row mapping + __ldcg loads
// (best instruction stream), block 256 (vs 512) for finer CTA scheduling
// granularity / higher achieved occupancy. Everything else identical to the
// reproduced-best kernel (35.4-36.5us band, DRAM 73-76%).
//
// Mapping:
//   lane i loads input cols [2i,2i+2) per subband (float2 via __ldcg,
//     256B/warp/subband, 4 front-batched LDG.64)
//   lane i stores output cols [4i,4i+4) of rows 2h and 2h+1 (float4 each,
//     512B fully contiguous per STG.128)

#define IWT_H 64
#define IWT_W 64
#define PLANE_IN  (IWT_H * IWT_W)          // 4096
#define PLANE_OUT (4 * IWT_H * IWT_W)      // 16384

__global__ void __launch_bounds__(256, 8) iwt_kernel(
    const float* __restrict__ x, float* __restrict__ out)
{
    int t = blockIdx.x * blockDim.x + threadIdx.x;
    int lane = t & 31;
    int w = t >> 5;          // warp index = (bc, h)
    int h = w & 63;
    int bc = w >> 6;         // 0 .. B*C-1 (2048)

    const float2* base = (const float2*)(x + (size_t)bc * 4 * PLANE_IN + h * IWT_W + 2 * lane);
    float2 a  = __ldcg(base);
    float2 hh = __ldcg(base + PLANE_IN / 2);
    float2 v  = __ldcg(base + 2 * PLANE_IN / 2);
    float2 d  = __ldcg(base + 3 * PLANE_IN / 2);

    float4 r0, r1;
    {
        float ai = a.x, hi = hh.x, vi = v.x, di = d.x;
        r0.x = (ai + hi + vi + di) * 0.5f;
        r0.y = (ai + hi - vi - di) * 0.5f;
        r1.x = (ai - hi + vi - di) * 0.5f;
        r1.y = (ai - hi - vi + di) * 0.5f;
    }
    {
        float ai = a.y, hi = hh.y, vi = v.y, di = d.y;
        r0.z = (ai + hi + vi + di) * 0.5f;
        r0.w = (ai + hi - vi - di) * 0.5f;
        r1.z = (ai - hi + vi - di) * 0.5f;
        r1.w = (ai - hi - vi + di) * 0.5f;
    }

    float* o = out + (size_t)bc * PLANE_OUT + (2 * h) * (2 * IWT_W) + 4 * lane;
    *(float4*)(o)              = r0;   // row 2h
    *(float4*)(o + 2 * IWT_W)  = r1;   // row 2h+1
}

extern "C" void kernel_launch(void* const* d_in, const int* in_sizes, int n_in,
                              void* d_out, int out_size) {
    const float* x = (const float*)d_in[0];
    float* out = (float*)d_out;

    int total = in_sizes[0];            // 33,554,432 elems
    int threads_total = total / 8;      // 8 elems per thread

    int threads = 256;
    int blocks = threads_total / threads;   // 16384
    iwt_kernel<<<blocks, threads>>>(x, out);
}

// round 16
// speedup vs baseline: 1.0109x; 1.0109x over previous
#include <cuda_runtime.h>
#include <cstdint>

// Inverse 2D Haar wavelet (synthesis), fixed shapes:
//   in : (B=32, C4=256, H=64, W=64) f32   (C4 = C*4: cA,cH,cV,cD per channel)
//   out: (B=32, C=64, 128, 128) f32
//
// FINAL KERNEL — best measured config across the full session
// (kernel 35.42us / bench 43.49us best; 35.4-36.5us band over 6 runs,
//  DRAM 73-76% of spec, rel_err 0.0 every run):
//
// Warp-per-input-row mapping:
//   lane i loads input cols [2i,2i+2) per subband (float2 via __ldcg,
//     256B/warp/subband, 4 front-batched LDG.64 -> MLP 4; __ldcg skips the
//     pointless L1 fill for this single-use stream)
//   lane i stores output cols [4i,4i+4) of rows 2h and 2h+1 (float4 each,
//     512B fully contiguous per STG.128 -> full-sector store wavefronts)
//
// Floor evidence (R1-R15): 268MB/pass compulsory traffic; ~22% capacity-bound
// L2 absorption under fixed-order graph replay (the persisting-L2 carveout
// that evict_last needs is forbidden by harness device-limit rules); ~75% of
// DRAM spec is the mixed R/W stream ceiling. Measured neutral or negative:
// 4-row tiles, evict_last/evict_first policy descriptors, .cs streaming
// stores, v8.b32 stores, persistent grid + software prefetch, block 256/512
// swaps. Compute and issue pipes all have 4-5x headroom throughout.

#define IWT_H 64
#define IWT_W 64
#define PLANE_IN  (IWT_H * IWT_W)          // 4096
#define PLANE_OUT (4 * IWT_H * IWT_W)      // 16384

__global__ void __launch_bounds__(512) iwt_kernel(
    const float* __restrict__ x, float* __restrict__ out)
{
    int t = blockIdx.x * blockDim.x + threadIdx.x;
    int lane = t & 31;
    int w = t >> 5;          // warp index = (bc, h)
    int h = w & 63;
    int bc = w >> 6;         // 0 .. B*C-1 (2048)

    const float2* base = (const float2*)(x + (size_t)bc * 4 * PLANE_IN + h * IWT_W + 2 * lane);
    float2 a  = __ldcg(base);
    float2 hh = __ldcg(base + PLANE_IN / 2);
    float2 v  = __ldcg(base + 2 * PLANE_IN / 2);
    float2 d  = __ldcg(base + 3 * PLANE_IN / 2);

    float4 r0, r1;
    {
        float ai = a.x, hi = hh.x, vi = v.x, di = d.x;
        r0.x = (ai + hi + vi + di) * 0.5f;
        r0.y = (ai + hi - vi - di) * 0.5f;
        r1.x = (ai - hi + vi - di) * 0.5f;
        r1.y = (ai - hi - vi + di) * 0.5f;
    }
    {
        float ai = a.y, hi = hh.y, vi = v.y, di = d.y;
        r0.z = (ai + hi + vi + di) * 0.5f;
        r0.w = (ai + hi - vi - di) * 0.5f;
        r1.z = (ai - hi + vi - di) * 0.5f;
        r1.w = (ai - hi - vi + di) * 0.5f;
    }

    float* o = out + (size_t)bc * PLANE_OUT + (2 * h) * (2 * IWT_W) + 4 * lane;
    *(float4*)(o)              = r0;   // row 2h
    *(float4*)(o + 2 * IWT_W)  = r1;   // row 2h+1
}

extern "C" void kernel_launch(void* const* d_in, const int* in_sizes, int n_in,
                              void* d_out, int out_size) {
    const float* x = (const float*)d_in[0];
    float* out = (float*)d_out;

    int total = in_sizes[0];            // 33,554,432 elems
    int threads_total = total / 8;      // 8 elems per thread

    int threads = 512;
    int blocks = threads_total / threads;   // 8192
    iwt_kernel<<<blocks, threads>>>(x, out);
}